// round 4
// baseline (speedup 1.0000x reference)
#include <cuda_runtime.h>

// y[b, i] = input[b, i] * diag(weight)[i] + bias[i]
// B = 8192, N = 4096, fp32.
//
// Single fused kernel, column-tiled:
//   block = 256 threads, each thread owns one float4 column lane (4 scalar cols)
//   gridDim.x = N/1024 = 4 column tiles
//   gridDim.y = B/ROWS_PER_BLOCK row tiles
// Thread loads its 4 diag values + bias once (registers), then streams rows
// with pure coalesced LDG.128 / STG.128, unrolled x4 for MLP.

#define N_COLS 4096
#define N4 (N_COLS / 4)          // 1024 float4 columns
#define THREADS 256
#define ROWS_PER_BLOCK 32

__global__ void __launch_bounds__(THREADS)
fused_diag_scale_bias(const float4* __restrict__ in,
                      const float*  __restrict__ weight,
                      const float4* __restrict__ bias4,
                      float4* __restrict__ out,
                      int rows) {
    // float4 column lane this thread owns
    int f4col = blockIdx.x * THREADS + threadIdx.x;   // 0..N4-1
    int col0  = f4col * 4;

    // Gather 4 diagonal values into registers.
    // weight[(c, c)] = weight[c * (N+1)] for row-major [N, N].
    float4 d;
    d.x = __ldg(&weight[(size_t)(col0 + 0) * (N_COLS + 1)]);
    d.y = __ldg(&weight[(size_t)(col0 + 1) * (N_COLS + 1)]);
    d.z = __ldg(&weight[(size_t)(col0 + 2) * (N_COLS + 1)]);
    d.w = __ldg(&weight[(size_t)(col0 + 3) * (N_COLS + 1)]);

    float4 b = bias4[f4col];

    int row0 = blockIdx.y * ROWS_PER_BLOCK;
    int base = row0 * N4 + f4col;

    #pragma unroll
    for (int r = 0; r < ROWS_PER_BLOCK; r += 4) {
        int i0 = base + (r + 0) * N4;
        int i1 = base + (r + 1) * N4;
        int i2 = base + (r + 2) * N4;
        int i3 = base + (r + 3) * N4;

        // Front-batched independent loads (MLP = 4)
        float4 x0 = in[i0];
        float4 x1 = in[i1];
        float4 x2 = in[i2];
        float4 x3 = in[i3];

        float4 y0, y1, y2, y3;
        y0.x = fmaf(x0.x, d.x, b.x); y0.y = fmaf(x0.y, d.y, b.y);
        y0.z = fmaf(x0.z, d.z, b.z); y0.w = fmaf(x0.w, d.w, b.w);
        y1.x = fmaf(x1.x, d.x, b.x); y1.y = fmaf(x1.y, d.y, b.y);
        y1.z = fmaf(x1.z, d.z, b.z); y1.w = fmaf(x1.w, d.w, b.w);
        y2.x = fmaf(x2.x, d.x, b.x); y2.y = fmaf(x2.y, d.y, b.y);
        y2.z = fmaf(x2.z, d.z, b.z); y2.w = fmaf(x2.w, d.w, b.w);
        y3.x = fmaf(x3.x, d.x, b.x); y3.y = fmaf(x3.y, d.y, b.y);
        y3.z = fmaf(x3.z, d.z, b.z); y3.w = fmaf(x3.w, d.w, b.w);

        out[i0] = y0;
        out[i1] = y1;
        out[i2] = y2;
        out[i3] = y3;
    }
}

extern "C" void kernel_launch(void* const* d_in, const int* in_sizes, int n_in,
                              void* d_out, int out_size) {
    const float* input  = (const float*)d_in[0];   // [B, N]
    const float* weight = (const float*)d_in[1];   // [N, N]
    const float* bias   = (const float*)d_in[2];   // [N]
    float* out = (float*)d_out;

    int rows = out_size / N_COLS;                  // B = 8192

    dim3 grid(N4 / THREADS,                        // 4 column tiles
              rows / ROWS_PER_BLOCK);              // 256 row tiles
    fused_diag_scale_bias<<<grid, THREADS>>>(
        reinterpret_cast<const float4*>(input),
        weight,
        reinterpret_cast<const float4*>(bias),
        reinterpret_cast<float4*>(out),
        rows);
}

// round 5
// speedup vs baseline: 1.0853x; 1.0853x over previous
#include <cuda_runtime.h>

// y[b, i] = input[b, i] * diag(weight)[i] + bias[i]
// B = 8192, N = 4096, fp32.
//
// Kernel 1: gather diag(weight) into __device__ scratch (tiny, ~1-2 us).
// Kernel 2: one block per row. Each thread handles 4 float4s at
//   tid, tid+256, tid+512, tid+768 within the row, so the diag/bias table
//   indices are blockIdx-invariant -> hoisted to registers, loaded once
//   per block from L1. Input loads front-batched (MLP=4), fully coalesced.

#define N_COLS 4096
#define N4 (N_COLS / 4)          // 1024 float4 columns = 1 row per block
#define THREADS 256
#define UNROLL 4

__device__ float g_diag[N_COLS];

__global__ void extract_diag_kernel(const float* __restrict__ weight, int n) {
    int i = blockIdx.x * blockDim.x + threadIdx.x;
    if (i < n) {
        g_diag[i] = weight[(size_t)i * (size_t)(n + 1)];
    }
}

__global__ void __launch_bounds__(THREADS)
scale_bias_kernel(const float4* __restrict__ in,
                  const float4* __restrict__ bias4,
                  float4* __restrict__ out) {
    const float4* __restrict__ d4 = reinterpret_cast<const float4*>(g_diag);
    int tid = threadIdx.x;

    // Block-invariant table values: column of element k is tid + k*THREADS.
    float4 d[UNROLL], b[UNROLL];
    #pragma unroll
    for (int k = 0; k < UNROLL; k++) {
        int c = tid + k * THREADS;
        d[k] = d4[c];
        b[k] = bias4[c];
    }

    int base = blockIdx.x * (THREADS * UNROLL) + tid;   // start of this row

    // Front-batched independent input loads (MLP = 4), coalesced LDG.128.
    float4 x[UNROLL];
    #pragma unroll
    for (int k = 0; k < UNROLL; k++) {
        x[k] = in[base + k * THREADS];
    }

    #pragma unroll
    for (int k = 0; k < UNROLL; k++) {
        float4 y;
        y.x = fmaf(x[k].x, d[k].x, b[k].x);
        y.y = fmaf(x[k].y, d[k].y, b[k].y);
        y.z = fmaf(x[k].z, d[k].z, b[k].z);
        y.w = fmaf(x[k].w, d[k].w, b[k].w);
        out[base + k * THREADS] = y;
    }
}

extern "C" void kernel_launch(void* const* d_in, const int* in_sizes, int n_in,
                              void* d_out, int out_size) {
    const float* input  = (const float*)d_in[0];   // [B, N]
    const float* weight = (const float*)d_in[1];   // [N, N]
    const float* bias   = (const float*)d_in[2];   // [N]
    float* out = (float*)d_out;

    // 1) gather diagonal
    extract_diag_kernel<<<(N_COLS + 255) / 256, 256>>>(weight, N_COLS);

    // 2) streaming scale + bias: one block per row
    int total4 = out_size / 4;                     // B * N4
    int blocks = total4 / (THREADS * UNROLL);      // = B = 8192
    scale_bias_kernel<<<blocks, THREADS>>>(
        reinterpret_cast<const float4*>(input),
        reinterpret_cast<const float4*>(bias),
        reinterpret_cast<float4*>(out));
}